// round 7
// baseline (speedup 1.0000x reference)
#include <cuda_runtime.h>

// Problem constants
#define Bn   1024
#define Hn   256
#define Gn   768      // 3*H
#define On   512
#define Tn   60
#define Cc   15
#define TB   10       // samples per CTA tile
#define HP   12       // padded h row (48B, 16B-aligned)
#define K4   64       // Hn/4
#define MAXT 116      // sum_c ceil(n_c/TB) <= 115, padded

// Device scratch (allocation-free rule: static __device__ arrays)
// Packed k4-interleaved layouts: W_p[((c*K4 + k4)*COLS + g)*4 + j] = W[c][g][4*k4+j]
// Padded by one k4 row so prefetch of k4+1 at k4=K4-1 stays in-bounds.
__device__ float g_Wi_p[Cc * K4 * Gn * 4 + Gn * 4];
__device__ float g_Wh_p[Cc * K4 * Gn * 4 + Gn * 4];
__device__ float g_Wc_p[Cc * K4 * On * 4 + On * 4];
__device__ int   g_perm[Bn];
__device__ int   g_tile_cam[MAXT];
__device__ int   g_tile_start[MAXT];
__device__ int   g_tile_cnt[MAXT];

typedef unsigned long long u64;

__device__ __forceinline__ u64 pack2(float a, float b) {
    u64 r;
    asm("mov.b64 %0, {%1, %2};" : "=l"(r)
        : "r"(__float_as_uint(a)), "r"(__float_as_uint(b)));
    return r;
}
__device__ __forceinline__ void fma2(u64 &d, u64 a, u64 b) {
    asm("fma.rn.f32x2 %0, %1, %2, %0;" : "+l"(d) : "l"(a), "l"(b));
}
__device__ __forceinline__ float2 unpack2(u64 v) {
    unsigned lo, hi;
    asm("mov.b64 {%0, %1}, %2;" : "=r"(lo), "=r"(hi) : "l"(v));
    return make_float2(__uint_as_float(lo), __uint_as_float(hi));
}
__device__ __forceinline__ float sigf(float v) {
    return 1.0f / (1.0f + __expf(-v));
}
__device__ __forceinline__ float tanh_f(float v) {
    return 2.0f * sigf(2.0f * v) - 1.0f;
}

// ---------------------------------------------------------------------------
// Kernel 0 (merged prep): all blocks repack weights (grid-stride); block 0
// additionally counting-sorts samples by camera and builds the tile table.
// Merging keeps launches/call at 2 so ncu's -s 5 lands on the main kernel.
// ---------------------------------------------------------------------------
__global__ void prep_kernel(const int* __restrict__ cam,
                            const float* __restrict__ Wi,
                            const float* __restrict__ Wh,
                            const float* __restrict__ Wc) {
    int idx    = blockIdx.x * blockDim.x + threadIdx.x;
    int stride = gridDim.x * blockDim.x;
    const int totA = Cc * K4 * Gn * 4;
    for (int i = idx; i < totA; i += stride) {
        int j  = i & 3;
        int g  = (i >> 2) % Gn;
        int k4 = ((i >> 2) / Gn) % K4;
        int c  = i / (4 * Gn * K4);
        int k  = 4 * k4 + j;
        g_Wi_p[i] = Wi[(c * Gn + g) * Hn + k];
        g_Wh_p[i] = Wh[(c * Gn + g) * Hn + k];
    }
    const int totC = Cc * K4 * On * 4;
    for (int i = idx; i < totC; i += stride) {
        int j  = i & 3;
        int o  = (i >> 2) % On;
        int k4 = ((i >> 2) / On) % K4;
        int c  = i / (4 * On * K4);
        int k  = 4 * k4 + j;
        g_Wc_p[i] = Wc[(c * On + o) * Hn + k];
    }

    if (blockIdx.x == 0) {
        __shared__ int cnts[Cc], offs[Cc], curs[Cc];
        int tid = threadIdx.x;
        if (tid < Cc) cnts[tid] = 0;
        __syncthreads();
        for (int b = tid; b < Bn; b += blockDim.x)
            atomicAdd(&cnts[cam[b]], 1);
        __syncthreads();
        if (tid == 0) {
            int o = 0;
            for (int c = 0; c < Cc; c++) { offs[c] = o; curs[c] = o; o += cnts[c]; }
        }
        __syncthreads();
        for (int b = tid; b < Bn; b += blockDim.x) {
            int p = atomicAdd(&curs[cam[b]], 1);
            g_perm[p] = b;
        }
        __syncthreads();
        if (tid == 0) {
            int t = 0;
            for (int c = 0; c < Cc; c++) {
                for (int s = 0; s < cnts[c]; s += TB) {
                    g_tile_cam[t]   = c;
                    g_tile_start[t] = offs[c] + s;
                    g_tile_cnt[t]   = min(TB, cnts[c] - s);
                    t++;
                }
            }
            for (; t < MAXT; t++) g_tile_cnt[t] = 0;
        }
    }
}

// ---------------------------------------------------------------------------
// Load 10 h values (one k-row, padded to HP=12) as 5 u64 sample-pairs.
// ---------------------------------------------------------------------------
__device__ __forceinline__ void load_hrow(const float* row, u64 hv[5]) {
    ulonglong2 a = *reinterpret_cast<const ulonglong2*>(row);      // s0s1,s2s3
    ulonglong2 b = *reinterpret_cast<const ulonglong2*>(row + 4);  // s4s5,s6s7
    u64        c = *reinterpret_cast<const u64*>(row + 8);         // s8s9
    hv[0] = a.x; hv[1] = a.y; hv[2] = b.x; hv[3] = b.y; hv[4] = c;
}

// ---------------------------------------------------------------------------
// Main persistent kernel: one CTA per TB-sample same-camera tile.
// 512 threads, warp-specialized pipeline:
//   threads 0-255   (A): iter i computes h_{i+1} from h_i   (i < T)
//   threads 256-511 (B): iter i computes out_{i-1} from h_i (i > 0)
// Weight loads are register-double-buffered (prefetch k4+1 while fma-ing k4)
// so L2 latency overlaps the fma2 pipe.
// ---------------------------------------------------------------------------
__global__ void __launch_bounds__(512, 1)
gru_main_kernel(const float* __restrict__ x,
                const float* __restrict__ b_ih,
                const float* __restrict__ b_hh,
                const float* __restrict__ bc,
                float* __restrict__ out) {
    extern __shared__ float sm[];
    float* sh_h  = sm;                         // [2][Hn][HP]  6144 floats
    float* sh_gi = sm + 2 * Hn * HP;           // [3][256][TB] 7680 floats
    float* sh_o  = sm + 2 * Hn * HP + 3 * 256 * TB;  // [256][2][TB][4] 20480 floats
    float* sh_x  = sh_o;                       // alias: setup-only lifetime [Hn][HP]
    int*   sh_samp = (int*)(sh_o + 256 * 2 * TB * 4);

    const int tile = blockIdx.x;
    const int cnt  = g_tile_cnt[tile];
    if (cnt == 0) return;
    const int cam   = g_tile_cam[tile];
    const int start = g_tile_start[tile];
    const int tid   = threadIdx.x;

    if (tid < TB) sh_samp[tid] = (tid < cnt) ? g_perm[start + tid] : 0;
    __syncthreads();

    // Init: x transposed into smem (zero-pad), both h buffers = 0.
    for (int i = tid; i < Hn * HP; i += 512) {
        int s = i % HP, k = i / HP;
        sh_x[i] = (s < cnt) ? x[sh_samp[s] * Hn + k] : 0.0f;
        sh_h[i] = 0.0f;
        sh_h[Hn * HP + i] = 0.0f;
    }
    __syncthreads();

    // ---- per-group setup --------------------------------------------------
    float bhn = 0.0f, bc0 = 0.0f, bc1 = 0.0f;
    int   ob[TB];

    if (tid < 256) {
        // A-group: gi = x @ Wi^T + b_ih (+ b_hh folded for r,z) -> smem.
        const int lt = tid;
        float aR[TB], aZ[TB], aN[TB];
#pragma unroll
        for (int s = 0; s < TB; s++) { aR[s] = 0.f; aZ[s] = 0.f; aN[s] = 0.f; }
        const float4* w = ((const float4*)g_Wi_p) + (size_t)cam * K4 * Gn;
        for (int k4 = 0; k4 < K4; k4++) {
            float4 w0 = w[lt], w1 = w[256 + lt], w2 = w[512 + lt];
            const float* f0 = (const float*)&w0;
            const float* f1 = (const float*)&w1;
            const float* f2 = (const float*)&w2;
#pragma unroll
            for (int j = 0; j < 4; j++) {
                const float* xk = &sh_x[(4 * k4 + j) * HP];
#pragma unroll
                for (int s = 0; s < TB; s++) {
                    float xv = xk[s];
                    aR[s] += f0[j] * xv;
                    aZ[s] += f1[j] * xv;
                    aN[s] += f2[j] * xv;
                }
            }
            w += Gn;
        }
        float br = b_ih[cam * Gn + lt]       + b_hh[cam * Gn + lt];
        float bz = b_ih[cam * Gn + 256 + lt] + b_hh[cam * Gn + 256 + lt];
        float bn = b_ih[cam * Gn + 512 + lt];
#pragma unroll
        for (int s = 0; s < TB; s++) {
            sh_gi[0 * 256 * TB + lt * TB + s] = aR[s] + br;
            sh_gi[1 * 256 * TB + lt * TB + s] = aZ[s] + bz;
            sh_gi[2 * 256 * TB + lt * TB + s] = aN[s] + bn;
        }
        bhn = b_hh[cam * Gn + 512 + lt];
    } else {
        const int lb = tid - 256;
        bc0 = bc[cam * On + lb];
        bc1 = bc[cam * On + 256 + lb];
#pragma unroll
        for (int s = 0; s < TB; s++) ob[s] = sh_samp[s] * (On * Tn);
    }

    const float4* whp = ((const float4*)g_Wh_p) + (size_t)cam * K4 * Gn;
    const float4* wcp = ((const float4*)g_Wc_p) + (size_t)cam * K4 * On;

    // ---- pipelined main loop: T+1 iterations ------------------------------
    for (int i = 0; i <= Tn; i++) {
        const int p = i & 1;
        const float* hb = sh_h + p * (Hn * HP);         // h_i (read-only)
        float*       hw = sh_h + (1 - p) * (Hn * HP);   // h_{i+1} (A writes)

        if (tid < 256) {
            if (i < Tn) {
                const int lt = tid;
                u64 aR[5], aZ[5], aN[5];
#pragma unroll
                for (int q = 0; q < 5; q++) { aR[q] = 0; aZ[q] = 0; aN[q] = 0; }
                const float4* w = whp;
                // prime the software pipeline
                float4 cR = w[lt], cZ = w[256 + lt], cN = w[512 + lt];
#pragma unroll 4
                for (int k4 = 0; k4 < K4; k4++) {
                    const float4* wn = w + Gn;
                    float4 nR = wn[lt], nZ = wn[256 + lt], nN = wn[512 + lt];
                    const float* fr = (const float*)&cR;
                    const float* fz = (const float*)&cZ;
                    const float* fn = (const float*)&cN;
#pragma unroll
                    for (int j = 0; j < 4; j++) {
                        u64 hv[5];
                        load_hrow(hb + (4 * k4 + j) * HP, hv);
                        u64 r2 = pack2(fr[j], fr[j]);
                        u64 z2 = pack2(fz[j], fz[j]);
                        u64 n2 = pack2(fn[j], fn[j]);
#pragma unroll
                        for (int q = 0; q < 5; q++) {
                            fma2(aR[q], r2, hv[q]);
                            fma2(aZ[q], z2, hv[q]);
                            fma2(aN[q], n2, hv[q]);
                        }
                    }
                    cR = nR; cZ = nZ; cN = nN;
                    w = wn;
                }
                // Gate epilogue -> h_{i+1}
                const float* hold = hb + lt * HP;
                float*       hnew = hw + lt * HP;
                const float* giR = &sh_gi[0 * 256 * TB + lt * TB];
                const float* giZ = &sh_gi[1 * 256 * TB + lt * TB];
                const float* giN = &sh_gi[2 * 256 * TB + lt * TB];
#pragma unroll
                for (int q = 0; q < 5; q++) {
                    float2 vR = unpack2(aR[q]);
                    float2 vZ = unpack2(aZ[q]);
                    float2 vN = unpack2(aN[q]);
                    int s0 = 2 * q, s1 = s0 + 1;
                    {
                        float r = sigf(giR[s0] + vR.x);
                        float z = sigf(giZ[s0] + vZ.x);
                        float n = tanh_f(giN[s0] + r * (vN.x + bhn));
                        hnew[s0] = (1.0f - z) * n + z * hold[s0];
                    }
                    {
                        float r = sigf(giR[s1] + vR.y);
                        float z = sigf(giZ[s1] + vZ.y);
                        float n = tanh_f(giN[s1] + r * (vN.y + bhn));
                        hnew[s1] = (1.0f - z) * n + z * hold[s1];
                    }
                }
            }
        } else {
            if (i > 0) {
                const int lb = tid - 256;
                const int t  = i - 1;
                u64 a0[5], a1[5];
#pragma unroll
                for (int q = 0; q < 5; q++) { a0[q] = 0; a1[q] = 0; }
                const float4* w = wcp;
                float4 c0 = w[lb], c1 = w[256 + lb];
#pragma unroll 4
                for (int k4 = 0; k4 < K4; k4++) {
                    const float4* wn = w + On;
                    float4 n0 = wn[lb], n1 = wn[256 + lb];
                    const float* f0 = (const float*)&c0;
                    const float* f1 = (const float*)&c1;
#pragma unroll
                    for (int j = 0; j < 4; j++) {
                        u64 hv[5];
                        load_hrow(hb + (4 * k4 + j) * HP, hv);
                        u64 p0 = pack2(f0[j], f0[j]);
                        u64 p1 = pack2(f1[j], f1[j]);
#pragma unroll
                        for (int q = 0; q < 5; q++) {
                            fma2(a0[q], p0, hv[q]);
                            fma2(a1[q], p1, hv[q]);
                        }
                    }
                    c0 = n0; c1 = n1;
                    w = wn;
                }
                // Stage sigmoid outputs into smem (thread-private slice).
                float* obuf = sh_o + lb * (2 * TB * 4);
                const int tq = t & 3;
#pragma unroll
                for (int q = 0; q < 5; q++) {
                    float2 v0 = unpack2(a0[q]);
                    float2 v1 = unpack2(a1[q]);
                    int s0 = 2 * q, s1 = s0 + 1;
                    obuf[(0 * TB + s0) * 4 + tq] = sigf(v0.x + bc0);
                    obuf[(1 * TB + s0) * 4 + tq] = sigf(v1.x + bc1);
                    obuf[(0 * TB + s1) * 4 + tq] = sigf(v0.y + bc0);
                    obuf[(1 * TB + s1) * 4 + tq] = sigf(v1.y + bc1);
                }
                // Flush every 4 timesteps with STG.128 (own slice, no barrier).
                if (tq == 3) {
                    const int t0 = t - 3;
#pragma unroll
                    for (int s = 0; s < TB; s++) {
                        if (s < cnt) {
                            float4 r0 = *reinterpret_cast<float4*>(&obuf[(0 * TB + s) * 4]);
                            float4 r1 = *reinterpret_cast<float4*>(&obuf[(1 * TB + s) * 4]);
                            *reinterpret_cast<float4*>(&out[ob[s] + lb * Tn + t0])         = r0;
                            *reinterpret_cast<float4*>(&out[ob[s] + (256 + lb) * Tn + t0]) = r1;
                        }
                    }
                }
            }
        }
        __syncthreads();   // publish h_{i+1}; retire reads of h_i
    }
}

// ---------------------------------------------------------------------------
extern "C" void kernel_launch(void* const* d_in, const int* in_sizes, int n_in,
                              void* d_out, int out_size) {
    const float* x    = (const float*)d_in[0];
    const int*   cam  = (const int*)  d_in[1];
    const float* W_ih = (const float*)d_in[2];
    const float* W_hh = (const float*)d_in[3];
    const float* b_ih = (const float*)d_in[4];
    const float* b_hh = (const float*)d_in[5];
    const float* Wc   = (const float*)d_in[6];
    const float* bc   = (const float*)d_in[7];
    float* out = (float*)d_out;

    const size_t smem = (size_t)(2 * Hn * HP + 3 * 256 * TB + 256 * 2 * TB * 4)
                        * sizeof(float) + 16 * sizeof(int);
    cudaFuncSetAttribute(gru_main_kernel,
                         cudaFuncAttributeMaxDynamicSharedMemorySize, (int)smem);

    prep_kernel<<<2048, 256>>>(cam, W_ih, W_hh, Wc);
    gru_main_kernel<<<MAXT, 512, smem>>>(x, b_ih, b_hh, bc, out);
}

// round 10
// speedup vs baseline: 1.2880x; 1.2880x over previous
#include <cuda_runtime.h>
#include <cuda_bf16.h>
#include <cstdint>

#define Bn 1024
#define Hn 256
#define Gn 768
#define On 512
#define Tn 60
#define Cc 15
#define MAXG 18
#define OT (On*Tn)

// Global scratch (allocation-free rule). Fragment-ordered weight planes.
__device__ __align__(16) uint32_t g_Bw[120 * 2 * 12288]; // gate B frags [tile][hi/lo][..]
__device__ __align__(16) uint32_t g_Bo[120 * 2 * 8192];  // out B frags
__device__ __align__(16) uint32_t g_Bx[120 * 2 * 12288]; // Wi B frags
__device__ __align__(16) uint32_t g_h[2 * MAXG * 2 * 16384]; // h words [par][grp][hi/lo][row*128+word]
__device__ int g_perm[Bn], g_gcam[MAXG], g_goff[MAXG], g_gcnt[MAXG], g_ngrp, g_bar[MAXG];

__device__ __forceinline__ float sigf(float v) { return 1.f / (1.f + __expf(-v)); }
__device__ __forceinline__ float tanhf_(float v) { return 2.f * sigf(2.f * v) - 1.f; }
__device__ __forceinline__ void bfsplit2(float f0, float f1, uint32_t& hi, uint32_t& lo) {
    unsigned short a = __bfloat16_as_ushort(__float2bfloat16_rn(f0));
    unsigned short b = __bfloat16_as_ushort(__float2bfloat16_rn(f1));
    float r0 = f0 - __uint_as_float((uint32_t)a << 16);
    float r1 = f1 - __uint_as_float((uint32_t)b << 16);
    unsigned short c = __bfloat16_as_ushort(__float2bfloat16_rn(r0));
    unsigned short d = __bfloat16_as_ushort(__float2bfloat16_rn(r1));
    hi = (uint32_t)a | ((uint32_t)b << 16);
    lo = (uint32_t)c | ((uint32_t)d << 16);
}
__device__ __forceinline__ void mma4(float* c, const uint32_t* a, uint32_t b0, uint32_t b1) {
    asm volatile("mma.sync.aligned.m16n8k16.row.col.f32.bf16.bf16.f32 "
                 "{%0,%1,%2,%3},{%4,%5,%6,%7},{%8,%9},{%0,%1,%2,%3};"
                 : "+f"(c[0]), "+f"(c[1]), "+f"(c[2]), "+f"(c[3])
                 : "r"(a[0]), "r"(a[1]), "r"(a[2]), "r"(a[3]), "r"(b0), "r"(b1));
}

// ---------------------------------------------------------------------------
__global__ void prep(const int* __restrict__ cam, const float* __restrict__ Wi,
                     const float* __restrict__ Wh, const float* __restrict__ Wc) {
    if (blockIdx.x == 0) {
        __shared__ int cn[Cc], cu[Cc], co[Cc];
        int tid = threadIdx.x;
        if (tid < Cc) cn[tid] = 0;
        if (tid < MAXG) g_bar[tid] = 0;
        __syncthreads();
        for (int b = tid; b < Bn; b += blockDim.x) atomicAdd(&cn[cam[b]], 1);
        __syncthreads();
        if (tid == 0) {
            int o = 0;
            for (int c = 0; c < Cc; c++) { co[c] = o; cu[c] = o; o += cn[c]; }
            int g = 0;
            for (int c = 0; c < Cc; c++)
                for (int s = 0; s < cn[c] && g < MAXG; s += 128) {
                    g_gcam[g] = c; g_goff[g] = co[c] + s; g_gcnt[g] = min(128, cn[c] - s); g++;
                }
            g_ngrp = g;
        }
        __syncthreads();
        for (int b = tid; b < Bn; b += blockDim.x) { int p = atomicAdd(&cu[cam[b]], 1); g_perm[p] = b; }
    }
    int idx = blockIdx.x * blockDim.x + threadIdx.x, st = gridDim.x * blockDim.x;
    const int NWG = 120 * 12 * 512;
    for (int i = idx; i < NWG; i += st) {
        int lane = i & 31, kc = (i >> 5) & 15, T = (i >> 9) % 12, tile = i / (512 * 12);
        int c = tile >> 3, j = tile & 7;
        size_t row = (size_t)c * Gn + (T >> 2) * 256 + 32 * j + 8 * (T & 3) + (lane >> 2);
        int k0 = 16 * kc + (lane & 3) * 2;
        size_t o = (size_t)tile * 24576 + (size_t)((T * 16 + kc) * 32 + lane) * 2;
        uint32_t h0, l0, h1, l1;
        const float* w = Wh + row * Hn;
        bfsplit2(w[k0], w[k0 + 1], h0, l0); bfsplit2(w[k0 + 8], w[k0 + 9], h1, l1);
        g_Bw[o] = h0; g_Bw[o + 1] = h1; g_Bw[o + 12288] = l0; g_Bw[o + 12289] = l1;
        w = Wi + row * Hn;
        bfsplit2(w[k0], w[k0 + 1], h0, l0); bfsplit2(w[k0 + 8], w[k0 + 9], h1, l1);
        g_Bx[o] = h0; g_Bx[o + 1] = h1; g_Bx[o + 12288] = l0; g_Bx[o + 12289] = l1;
    }
    const int NWO = 120 * 8 * 512;
    for (int i = idx; i < NWO; i += st) {
        int lane = i & 31, kc = (i >> 5) & 15, T = (i >> 9) & 7, tile = i / (512 * 8);
        int c = tile >> 3, j = tile & 7;
        const float* w = Wc + ((size_t)c * On + 64 * j + 8 * T + (lane >> 2)) * Hn;
        int k0 = 16 * kc + (lane & 3) * 2;
        size_t o = (size_t)tile * 16384 + (size_t)((T * 16 + kc) * 32 + lane) * 2;
        uint32_t h0, l0, h1, l1;
        bfsplit2(w[k0], w[k0 + 1], h0, l0); bfsplit2(w[k0 + 8], w[k0 + 9], h1, l1);
        g_Bo[o] = h0; g_Bo[o + 1] = h1; g_Bo[o + 8192] = l0; g_Bo[o + 8193] = l1;
    }
}

// ---------------------------------------------------------------------------
__global__ void __launch_bounds__(256, 1)
gru(const float* __restrict__ x, const float* __restrict__ b_ih,
    const float* __restrict__ b_hh, const float* __restrict__ bc,
    float* __restrict__ out) {
    extern __shared__ __align__(16) uint32_t sm[];
    uint32_t* sB  = sm;                  // 24576 u32 gate frags
    uint32_t* sBo = sm + 24576;          // 16384 u32 out frags
    float* sgi = (float*)(sm + 40960);   // 12288 floats
    float* bcs = (float*)(sm + 53248);   // 64
    float* bhs = (float*)(sm + 53312);   // 32
    int* samp  = (int*)(sm + 53344);     // 128

    const int grp = blockIdx.x >> 3, j = blockIdx.x & 7;
    if (grp >= g_ngrp) return;
    const int cam = g_gcam[grp], off = g_goff[grp], cnt = g_gcnt[grp];
    const int tile = cam * 8 + j;
    const int tid = threadIdx.x, wid = tid >> 5, lane = tid & 31;
    const bool act = (16 * wid) < cnt;
    const int r0 = 16 * wid + (lane >> 2), r1 = r0 + 8;

    if (tid < 128) samp[tid] = (tid < cnt) ? g_perm[off + tid] : 0;
    if (tid < 64) bcs[tid] = bc[cam * On + 64 * j + tid];
    if (tid < 32) bhs[tid] = b_hh[cam * Gn + 512 + 32 * j + tid];
    {
        const uint4* s = (const uint4*)(g_Bw + (size_t)tile * 24576);
        uint4* d = (uint4*)sB;
        for (int i = tid; i < 6144; i += 256) d[i] = s[i];
        const uint4* s2 = (const uint4*)(g_Bo + (size_t)tile * 16384);
        uint4* d2 = (uint4*)sBo;
        for (int i = tid; i < 4096; i += 256) d2[i] = s2[i];
    }
    __syncthreads();

    // gi = x@Wi + biases -> sgi (fragment-ordered, per-thread slot)
    if (act) {
        float acc[48];
#pragma unroll
        for (int q = 0; q < 48; q++) acc[q] = 0.f;
        const uint32_t* bx = g_Bx + (size_t)tile * 24576;
        const float* x0 = (r0 < cnt) ? x + (size_t)samp[r0] * Hn : 0;
        const float* x1 = (r1 < cnt) ? x + (size_t)samp[r1] * Hn : 0;
        for (int kc = 0; kc < 16; kc++) {
            int k0 = 16 * kc + (lane & 3) * 2;
            float2 p00 = x0 ? *(const float2*)(x0 + k0) : make_float2(0.f, 0.f);
            float2 p02 = x0 ? *(const float2*)(x0 + k0 + 8) : make_float2(0.f, 0.f);
            float2 p10 = x1 ? *(const float2*)(x1 + k0) : make_float2(0.f, 0.f);
            float2 p12 = x1 ? *(const float2*)(x1 + k0 + 8) : make_float2(0.f, 0.f);
            uint32_t ah[4], al[4];
            bfsplit2(p00.x, p00.y, ah[0], al[0]);
            bfsplit2(p10.x, p10.y, ah[1], al[1]);
            bfsplit2(p02.x, p02.y, ah[2], al[2]);
            bfsplit2(p12.x, p12.y, ah[3], al[3]);
#pragma unroll
            for (int T = 0; T < 12; T++) {
                size_t o = (size_t)((T * 16 + kc) * 32 + lane) * 2;
                uint2 bh = *(const uint2*)(bx + o);
                uint2 bl = *(const uint2*)(bx + 12288 + o);
                mma4(acc + 4 * T, ah, bh.x, bh.y);
                mma4(acc + 4 * T, ah, bl.x, bl.y);
                mma4(acc + 4 * T, al, bh.x, bh.y);
            }
        }
#pragma unroll
        for (int T = 0; T < 12; T++) {
            int g = T >> 2;
            int col = g * 256 + 32 * j + 8 * (T & 3) + (lane & 3) * 2;
            float b0 = b_ih[cam * Gn + col], b1 = b_ih[cam * Gn + col + 1];
            if (g < 2) { b0 += b_hh[cam * Gn + col]; b1 += b_hh[cam * Gn + col + 1]; }
            *(float4*)&sgi[tid * 48 + 4 * T] =
                make_float4(acc[4 * T] + b0, acc[4 * T + 1] + b1, acc[4 * T + 2] + b0, acc[4 * T + 3] + b1);
        }
    }
    float hold[16];
#pragma unroll
    for (int q = 0; q < 16; q++) hold[q] = 0.f;
    int bt = 0;

    for (int i = 0; i <= Tn; i++) {
        float gacc[48], oacc[32];
        if (act) {
#pragma unroll
            for (int q = 0; q < 48; q++) gacc[q] = 0.f;
#pragma unroll
            for (int q = 0; q < 32; q++) oacc[q] = 0.f;
            if (i > 0) {  // fused gate(+out) GEMM on h_i (h_0 == 0 -> skip at i=0)
                const uint32_t* hb = g_h + (size_t)((i & 1) * MAXG + grp) * 2 * 16384;
                const bool dog = i < Tn;
                for (int kc = 0; kc < 16; kc++) {
                    int w0 = (lane & 3) + 8 * kc, w1 = w0 + 4;
                    uint32_t ah[4], al[4];
                    ah[0] = hb[r0 * 128 + w0]; ah[1] = hb[r1 * 128 + w0];
                    ah[2] = hb[r0 * 128 + w1]; ah[3] = hb[r1 * 128 + w1];
                    al[0] = hb[16384 + r0 * 128 + w0]; al[1] = hb[16384 + r1 * 128 + w0];
                    al[2] = hb[16384 + r0 * 128 + w1]; al[3] = hb[16384 + r1 * 128 + w1];
                    if (dog) {
#pragma unroll
                        for (int T = 0; T < 12; T++) {
                            size_t o = (size_t)((T * 16 + kc) * 32 + lane) * 2;
                            uint2 bh = *(const uint2*)(sB + o);
                            uint2 bl = *(const uint2*)(sB + 12288 + o);
                            mma4(gacc + 4 * T, ah, bh.x, bh.y);
                            mma4(gacc + 4 * T, ah, bl.x, bl.y);
                            mma4(gacc + 4 * T, al, bh.x, bh.y);
                        }
                    }
#pragma unroll
                    for (int T = 0; T < 8; T++) {
                        size_t o = (size_t)((T * 16 + kc) * 32 + lane) * 2;
                        uint2 bh = *(const uint2*)(sBo + o);
                        uint2 bl = *(const uint2*)(sBo + 8192 + o);
                        mma4(oacc + 4 * T, ah, bh.x, bh.y);
                        mma4(oacc + 4 * T, ah, bl.x, bl.y);
                        mma4(oacc + 4 * T, al, bh.x, bh.y);
                    }
                }
            }
            if (i < Tn) {  // gate epilogue -> h_{i+1}
                uint32_t* dh = g_h + (size_t)(((i + 1) & 1) * MAXG + grp) * 2 * 16384;
#pragma unroll
                for (int tt = 0; tt < 4; tt++) {
                    float4 gr = *(float4*)&sgi[tid * 48 + 4 * tt];
                    float4 gz = *(float4*)&sgi[tid * 48 + 16 + 4 * tt];
                    float4 gn = *(float4*)&sgi[tid * 48 + 32 + 4 * tt];
                    int cb = 8 * tt + (lane & 3) * 2;
                    float bn0 = bhs[cb], bn1 = bhs[cb + 1];
                    float h0, h1, h2, h3;
                    { float r = sigf(gr.x + gacc[4 * tt]);     float z = sigf(gz.x + gacc[16 + 4 * tt]);
                      float n = tanhf_(gn.x + r * (gacc[32 + 4 * tt] + bn0));
                      h0 = (1.f - z) * n + z * hold[4 * tt];     hold[4 * tt] = h0; }
                    { float r = sigf(gr.y + gacc[4 * tt + 1]); float z = sigf(gz.y + gacc[16 + 4 * tt + 1]);
                      float n = tanhf_(gn.y + r * (gacc[32 + 4 * tt + 1] + bn1));
                      h1 = (1.f - z) * n + z * hold[4 * tt + 1]; hold[4 * tt + 1] = h1; }
                    { float r = sigf(gr.z + gacc[4 * tt + 2]); float z = sigf(gz.z + gacc[16 + 4 * tt + 2]);
                      float n = tanhf_(gn.z + r * (gacc[32 + 4 * tt + 2] + bn0));
                      h2 = (1.f - z) * n + z * hold[4 * tt + 2]; hold[4 * tt + 2] = h2; }
                    { float r = sigf(gr.w + gacc[4 * tt + 3]); float z = sigf(gz.w + gacc[16 + 4 * tt + 3]);
                      float n = tanhf_(gn.w + r * (gacc[32 + 4 * tt + 3] + bn1));
                      h3 = (1.f - z) * n + z * hold[4 * tt + 3]; hold[4 * tt + 3] = h3; }
                    uint32_t w0h, w0l, w1h, w1l;
                    bfsplit2(h0, h1, w0h, w0l);
                    bfsplit2(h2, h3, w1h, w1l);
                    int wrd = 16 * j + 4 * tt + (lane & 3);
                    dh[r0 * 128 + wrd] = w0h; dh[r1 * 128 + wrd] = w1h;
                    dh[16384 + r0 * 128 + wrd] = w0l; dh[16384 + r1 * 128 + wrd] = w1l;
                }
            }
            if (i > 0) {  // out epilogue: t = i-1
#pragma unroll
                for (int ot = 0; ot < 8; ot++) {
                    int cl = 8 * ot + (lane & 3) * 2;
                    float b0 = bcs[cl], b1 = bcs[cl + 1];
                    int col = 64 * j + cl;
                    if (r0 < cnt) {
                        float* p = out + (size_t)samp[r0] * OT + (size_t)col * Tn + (i - 1);
                        p[0] = sigf(oacc[4 * ot] + b0); p[Tn] = sigf(oacc[4 * ot + 1] + b1);
                    }
                    if (r1 < cnt) {
                        float* p = out + (size_t)samp[r1] * OT + (size_t)col * Tn + (i - 1);
                        p[0] = sigf(oacc[4 * ot + 2] + b0); p[Tn] = sigf(oacc[4 * ot + 3] + b1);
                    }
                }
            }
        }
        if (i < Tn) {  // per-group barrier (8 CTAs, all resident)
            __threadfence();
            __syncthreads();
            bt += 8;
            if (tid == 0) {
                atomicAdd(&g_bar[grp], 1);
                int v;
                do {
                    asm volatile("ld.global.acquire.gpu.b32 %0,[%1];" : "=r"(v) : "l"(&g_bar[grp]) : "memory");
                } while (v < bt);
            }
            __syncthreads();
        }
    }
}

// ---------------------------------------------------------------------------
extern "C" void kernel_launch(void* const* d_in, const int* in_sizes, int n_in,
                              void* d_out, int out_size) {
    const float* x    = (const float*)d_in[0];
    const int*   cam  = (const int*)  d_in[1];
    const float* W_ih = (const float*)d_in[2];
    const float* W_hh = (const float*)d_in[3];
    const float* b_ih = (const float*)d_in[4];
    const float* b_hh = (const float*)d_in[5];
    const float* Wc   = (const float*)d_in[6];
    const float* bc   = (const float*)d_in[7];
    float* out = (float*)d_out;
    const int smem = 53472 * 4;
    cudaFuncSetAttribute(gru, cudaFuncAttributeMaxDynamicSharedMemorySize, smem);
    prep<<<1024, 256>>>(cam, W_ih, W_hh, Wc);
    gru<<<MAXG * 8, 256, smem>>>(x, b_ih, b_hh, bc, out);
}